// round 7
// baseline (speedup 1.0000x reference)
#include <cuda_runtime.h>
#include <math.h>

// Problem constants
#define KK 64
#define DD 64
#define BB 16
#define NTOK 16384
#define TT 64                           // tokens per chunk
#define NCHUNK_TOTAL (BB * NTOK / TT)   // 4096 chunks
#define CH_PER_B (NTOK / TT)            // 256 chunks per batch
#define GRID 296                        // 148 SMs x occ 2, single wave
#define NTHREADS 256
#define PSIZE (KK + 2 * KK * DD)        // 8256 partial floats per slot

#define WSTRIDE 132                     // W_sh row stride (conflict-free)
#define FSTRIDE 132                     // f_sh row stride [x^2|x]
#define QSTRIDE 132                     // Ldup row stride (dup pairs, 128 used)
#define LOG2E 1.4426950408889634f
#define LN2PI 1.8378770664093453f

// smem layout (floats): W[64*132] | f[64*132] | Ldup[64*132] | c[64] | qsw[8*66]
#define SM_W 0
#define SM_F (64 * WSTRIDE)                  // 8448
#define SM_Q (SM_F + 64 * FSTRIDE)           // 16896
#define SM_C (SM_Q + 64 * QSTRIDE)           // 25344
#define SM_QS (SM_C + 64)                    // 25408
#define SMEM_FLOATS (SM_QS + 8 * 66)         // 25936
#define SMEM_BYTES (SMEM_FLOATS * 4)         // 103744 (x2 <= 227KB)

__device__ float g_scratch[GRID * 2 * PSIZE];
__device__ int   g_tag[GRID * 2];

typedef unsigned long long ull;

// ---------------- packed f32x2 helpers (sm_100+) ----------------
__device__ __forceinline__ void fma2(ull &d, ull a, ull b) {
    asm("fma.rn.f32x2 %0, %1, %2, %0;" : "+l"(d) : "l"(a), "l"(b));
}
__device__ __forceinline__ float2 unpk(ull v) {
    float2 r;
    asm("mov.b64 {%0, %1}, %2;" : "=f"(r.x), "=f"(r.y) : "l"(v));
    return r;
}
__device__ __forceinline__ float ex2f(float x) {
    float r;
    asm("ex2.approx.f32 %0, %1;" : "=f"(r) : "f"(x));
    return r;
}
// store a duplicated pair {v, v} with one STS.64, no pack needed
__device__ __forceinline__ void sts64dup(float* dst_sh, float v) {
    unsigned saddr = (unsigned)__cvta_generic_to_shared(dst_sh);
    asm volatile("st.shared.v2.f32 [%0], {%1, %1};" :: "r"(saddr), "f"(v));
}

// ---------------- main kernel (persistent, occ 2) -----------------
extern __shared__ float smem[];

__global__ __launch_bounds__(NTHREADS, 2)
void fv_main_kernel(const float* __restrict__ x,
                    const float* __restrict__ pi,
                    const float* __restrict__ mu,
                    const float* __restrict__ var) {
    float* W_sh  = smem + SM_W;
    float* f_sh  = smem + SM_F;
    float* Q_sh  = smem + SM_Q;    // logits then responsibilities, dup pairs
    float* c_sh  = smem + SM_C;
    float* qs_sh = smem + SM_QS;   // per-warp Q_sum partials [8][66]

    const int tid = threadIdx.x;
    const int bid = blockIdx.x;

    // chunk range for this CTA
    const int s_lo = (bid * NCHUNK_TOTAL) / GRID;
    const int s_hi = ((bid + 1) * NCHUNK_TOTAL) / GRID;

    const float4* xg = (const float4*)x;

    // prefetch first chunk (latency overlapped with prep)
    float4 pf[4];
#pragma unroll
    for (int it = 0; it < 4; it++)
        pf[it] = xg[(size_t)s_lo * 1024 + tid + NTHREADS * it];

    // ---- prep: fold weights/constants into smem (per-CTA) ----
    for (int i = tid; i < KK * 128; i += NTHREADS) {
        int k = i >> 7, j = i & 127, d = j & 63;
        float v = var[k * DD + d];
        float iv = __frcp_rn(v);
        float w = (j < 64) ? (-0.5f * iv * LOG2E) : (mu[k * DD + d] * iv * LOG2E);
        W_sh[k * WSTRIDE + j] = w;
    }
    {   // c[k] = (-0.5*(D ln2pi + sum(log v + m^2/v)) + ln pi)*log2e
        int k = tid >> 2, seg = tid & 3;
        float part = 0.f;
#pragma unroll 4
        for (int d = seg * 16; d < seg * 16 + 16; d++) {
            float v = var[k * DD + d];
            float m = mu[k * DD + d];
            part += __logf(v) + m * m * __frcp_rn(v);
        }
        part += __shfl_xor_sync(0xffffffffu, part, 1);
        part += __shfl_xor_sync(0xffffffffu, part, 2);
        if (seg == 0)
            c_sh[k] = (-0.5f * (64.0f * LN2PI + part) + __logf(pi[k])) * LOG2E;
    }

    // phase-3 accumulators: thread (ki, di) owns k in {ki+16i}, d quad 4di..4di+3
    const int ki = tid >> 4;
    const int di = tid & 15;
    ull aqx[4][2], aqx2[4][2];
#pragma unroll
    for (int i = 0; i < 4; i++) {
        aqx[i][0] = 0ull; aqx[i][1] = 0ull;
        aqx2[i][0] = 0ull; aqx2[i][1] = 0ull;
    }
    // per-warp Q_sum partials (k = lane, lane+32), accumulated in softmax
    float qs0 = 0.f, qs1 = 0.f;

    int slot = 0;
    int cur_b = s_lo / CH_PER_B;

    // phase-1 mapping: tokens tg+16*t4, k = 4*kg+k4
    const int tg = tid & 15;
    const int kg = tid >> 4;
    const int wid = tid >> 5;
    const int lane = tid & 31;

    for (int c = s_lo; c < s_hi; c++) {
        __syncthreads();   // f/Q reuse barrier (covers prep on first iter)

        // ---- phase 0: stage f = [x^2 | x] from prefetch regs ----
#pragma unroll
        for (int it = 0; it < 4; it++) {
            int f4 = tid + NTHREADS * it;       // 0..1023
            int t  = f4 >> 4;
            int c4 = f4 & 15;
            float4 v = pf[it];
            float* frow = f_sh + t * FSTRIDE;
            *(float4*)(frow + 64 + 4 * c4) = v;
            float4 s;
            s.x = v.x * v.x; s.y = v.y * v.y; s.z = v.z * v.z; s.w = v.w * v.w;
            *(float4*)(frow + 4 * c4) = s;
        }
        __syncthreads();

        // ---- phase 1: logits; 4 tokens x 4 k; wv held, fv streamed ----
        {
            ull acc[4][4];
#pragma unroll
            for (int a = 0; a < 4; a++)
#pragma unroll
                for (int cc = 0; cc < 4; cc++) acc[a][cc] = 0ull;

            const float* wbase = W_sh + (kg * 4) * WSTRIDE;
#pragma unroll 2
            for (int jp2 = 0; jp2 < 32; jp2++) {
                ulonglong2 wv[4];
#pragma unroll
                for (int k4 = 0; k4 < 4; k4++)
                    wv[k4] = *(const ulonglong2*)(wbase + k4 * WSTRIDE + 4 * jp2);
#pragma unroll
                for (int t4 = 0; t4 < 4; t4++) {
                    ulonglong2 fv = *(const ulonglong2*)(f_sh + (tg + 16 * t4) * FSTRIDE + 4 * jp2);
#pragma unroll
                    for (int k4 = 0; k4 < 4; k4++) {
                        fma2(acc[t4][k4], fv.x, wv[k4].x);
                        fma2(acc[t4][k4], fv.y, wv[k4].y);
                    }
                }
            }
            // epilogue: write duplicated (l,l) pairs
#pragma unroll
            for (int t4 = 0; t4 < 4; t4++) {
                int t = tg + 16 * t4;
#pragma unroll
                for (int k4 = 0; k4 < 4; k4++) {
                    int k = 4 * kg + k4;
                    float2 a = unpk(acc[t4][k4]);
                    sts64dup(Q_sh + t * QSTRIDE + 2 * k, a.x + a.y + c_sh[k]);
                }
            }
        }
        __syncthreads();

        // prefetch next chunk (covered by softmax + phase 3; low reg pressure here)
        if (c + 1 < s_hi) {
#pragma unroll
            for (int it = 0; it < 4; it++)
                pf[it] = xg[(size_t)(c + 1) * 1024 + tid + NTHREADS * it];
        }

        // ---- phase 2: softmax over K=64 per token; also build Q_sum ----
        {
#pragma unroll
            for (int t8 = 0; t8 < 8; t8++) {
                int t = wid * 8 + t8;
                float l0 = Q_sh[t * QSTRIDE + 2 * lane];
                float l1 = Q_sh[t * QSTRIDE + 2 * lane + 64];
                float m = fmaxf(l0, l1);
#pragma unroll
                for (int o = 16; o > 0; o >>= 1)
                    m = fmaxf(m, __shfl_xor_sync(0xffffffffu, m, o));
                float e0 = ex2f(l0 - m);
                float e1 = ex2f(l1 - m);
                float ssum = e0 + e1;
#pragma unroll
                for (int o = 16; o > 0; o >>= 1)
                    ssum += __shfl_xor_sync(0xffffffffu, ssum, o);
                float inv = __frcp_rn(ssum);
                float q0 = e0 * inv;
                float q1 = e1 * inv;
                sts64dup(Q_sh + t * QSTRIDE + 2 * lane, q0);
                sts64dup(Q_sh + t * QSTRIDE + 2 * lane + 64, q1);
                qs0 += q0;
                qs1 += q1;
            }
        }
        __syncthreads();

        // ---- phase 3: accumulate Q^T x, Q^T x^2 (dup-pair q via LDS.64) ----
        {
#pragma unroll 2
            for (int t = 0; t < TT; t++) {
                const float* frow = f_sh + t * FSTRIDE;
                const float* qrow = Q_sh + t * QSTRIDE;
                ulonglong2 sq = *(const ulonglong2*)(frow + 4 * di);       // x^2 quad
                ulonglong2 xq = *(const ulonglong2*)(frow + 64 + 4 * di);  // x quad
#pragma unroll
                for (int i = 0; i < 4; i++) {
                    ull q2 = *(const ull*)(qrow + 2 * (ki + 16 * i));      // (q,q)
                    fma2(aqx[i][0], q2, xq.x);
                    fma2(aqx[i][1], q2, xq.y);
                    fma2(aqx2[i][0], q2, sq.x);
                    fma2(aqx2[i][1], q2, sq.y);
                }
            }
        }

        // ---- flush partials at batch boundary / end of range ----
        int nb = (c + 1) / CH_PER_B;
        if (c + 1 == s_hi || nb != cur_b) {
            __syncthreads();
            qs_sh[wid * 66 + lane]      = qs0;
            qs_sh[wid * 66 + lane + 32] = qs1;
            __syncthreads();

            float* outp = g_scratch + (size_t)(bid * 2 + slot) * PSIZE;
            if (tid == 0) g_tag[bid * 2 + slot] = cur_b;
            if (di == 0) {
#pragma unroll
                for (int i = 0; i < 4; i++) {
                    int k = ki + 16 * i;
                    float qsk = 0.f;
#pragma unroll
                    for (int w = 0; w < 8; w++) qsk += qs_sh[w * 66 + k];
                    outp[k] = qsk;
                }
            }
#pragma unroll
            for (int i = 0; i < 4; i++) {
                int k = ki + 16 * i;
                float2 v0 = unpk(aqx[i][0]);
                float2 v1 = unpk(aqx[i][1]);
                float4 o; o.x = v0.x; o.y = v0.y; o.z = v1.x; o.w = v1.y;
                *(float4*)(outp + 64 + k * 64 + 4 * di) = o;
                float2 w0 = unpk(aqx2[i][0]);
                float2 w1 = unpk(aqx2[i][1]);
                float4 o2; o2.x = w0.x; o2.y = w0.y; o2.z = w1.x; o2.w = w1.y;
                *(float4*)(outp + 64 + 4096 + k * 64 + 4 * di) = o2;
            }
#pragma unroll
            for (int i = 0; i < 4; i++) {
                aqx[i][0] = 0ull; aqx[i][1] = 0ull;
                aqx2[i][0] = 0ull; aqx2[i][1] = 0ull;
            }
            qs0 = 0.f; qs1 = 0.f;
            slot++;
            cur_b = nb;
        }
    }
    if (tid == 0) {
        for (int sl = slot; sl < 2; sl++) g_tag[bid * 2 + sl] = -1;
    }
}

// ---------------- reduce + finalize ------------------------------
__global__ void fv_reduce_kernel(const float* __restrict__ pi,
                                 const float* __restrict__ mu,
                                 const float* __restrict__ var,
                                 float* __restrict__ out) {
    int idx = blockIdx.x * blockDim.x + threadIdx.x;   // 0 .. B*K*D-1
    if (idx >= BB * KK * DD) return;
    int b  = idx >> 12;
    int kd = idx & 4095;
    int k  = kd >> 6;
    int d  = kd & 63;

    // CTAs whose chunk range can overlap batch b (monotone partition)
    int i_lo = (GRID * b) / BB - 1;       if (i_lo < 0) i_lo = 0;
    int i_hi = (GRID * (b + 1)) / BB + 1; if (i_hi > GRID - 1) i_hi = GRID - 1;

    float qs = 0.f, qx = 0.f, qx2 = 0.f;
    float qsB = 0.f, qxB = 0.f, qx2B = 0.f;   // second accumulator for MLP
    int n = 2 * (i_hi - i_lo + 1);
    int base_sid = 2 * i_lo;
#pragma unroll 2
    for (int j = 0; j < n; j += 2) {
        int sid0 = base_sid + j;
        int sid1 = base_sid + j + 1;
        if (g_tag[sid0] == b) {
            const float* p = g_scratch + (size_t)sid0 * PSIZE;
            qs  += p[k];
            qx  += p[64 + kd];
            qx2 += p[64 + 4096 + kd];
        }
        if (g_tag[sid1] == b) {
            const float* p = g_scratch + (size_t)sid1 * PSIZE;
            qsB  += p[k];
            qxB  += p[64 + kd];
            qx2B += p[64 + 4096 + kd];
        }
    }
    qs += qsB; qx += qxB; qx2 += qx2B;

    const float invN = 1.0f / (float)NTOK;
    qs *= invN; qx *= invN; qx2 *= invN;

    float m = mu[kd];
    float v = var[kd];
    float* ob = out + (size_t)b * 8256;
    ob[64 + kd]        = qx - qs * m;
    ob[64 + 4096 + kd] = -qx2 - qs * m * m + qs * v + 2.0f * qx * m;
    if (d == 0) ob[k] = qs - pi[k];
}

// ---------------- launch -----------------------------------------
extern "C" void kernel_launch(void* const* d_in, const int* in_sizes, int n_in,
                              void* d_out, int out_size) {
    const float* x   = (const float*)d_in[0];
    const float* pi  = (const float*)d_in[1];
    const float* mu  = (const float*)d_in[2];
    const float* var = (const float*)d_in[3];
    float* out = (float*)d_out;

    cudaFuncSetAttribute(fv_main_kernel,
                         cudaFuncAttributeMaxDynamicSharedMemorySize, SMEM_BYTES);

    fv_main_kernel<<<GRID, NTHREADS, SMEM_BYTES>>>(x, pi, mu, var);
    fv_reduce_kernel<<<(BB * KK * DD + 255) / 256, 256>>>(pi, mu, var, out);
}

// round 9
// speedup vs baseline: 2.2854x; 2.2854x over previous
#include <cuda_runtime.h>
#include <cuda_bf16.h>
#include <math.h>

#define BB 16
#define NTOK 16384
#define TT 64
#define NCHUNK_TOTAL 4096
#define CH_PER_B 256
#define GRID 296
#define NTHREADS 256
#define PSIZE 8256
#define LOG2E 1.4426950408889634f
#define LN2PI 1.8378770664093453f

// smem byte offsets
#define SM_STAGE 0           // 64 x 272B: raw x f32 [64][68]; reused as logits L
#define SM_FH 17408          // 64 x 272B bf16 [x^2(0-63) | x(64-127)] hi
#define SM_FL 34816
#define SM_WH 52224          // 64 x 272B bf16 [Ws | Wx] hi   (row = k_gmm)
#define SM_WL 69632
#define SM_QH 87040          // 64 x 144B bf16 Q hi (row = token)
#define SM_QL 96256
#define SM_C  105472         // 64 f32
#define SM_QS 105728         // 8*66 f32
#define SMEM_BYTES 107840    // x2 CTAs = 215680 <= 228KB

__device__ float g_scratch[GRID * 2 * PSIZE];
__device__ int   g_tag[GRID * 2];

typedef unsigned int u32;
typedef unsigned short u16;

__device__ __forceinline__ u32 smem_u32(const void* p) {
    u32 a;
    asm("{ .reg .u64 t; cvta.to.shared.u64 t, %1; cvt.u32.u64 %0, t; }" : "=r"(a) : "l"(p));
    return a;
}
__device__ __forceinline__ float ex2f(float x) {
    float r; asm("ex2.approx.f32 %0, %1;" : "=f"(r) : "f"(x)); return r;
}
__device__ __forceinline__ void cpasync16(u32 dst, const float* src) {
    asm volatile("cp.async.cg.shared.global [%0], [%1], 16;" :: "r"(dst), "l"(src));
}
__device__ __forceinline__ void cpcommit() { asm volatile("cp.async.commit_group;"); }
__device__ __forceinline__ void cpwait0()  { asm volatile("cp.async.wait_group 0;"); }

__device__ __forceinline__ void ldsm4(u32 a, u32& r0, u32& r1, u32& r2, u32& r3) {
    asm volatile("ldmatrix.sync.aligned.m8n8.x4.shared.b16 {%0,%1,%2,%3}, [%4];"
                 : "=r"(r0), "=r"(r1), "=r"(r2), "=r"(r3) : "r"(a));
}
__device__ __forceinline__ void ldsm4t(u32 a, u32& r0, u32& r1, u32& r2, u32& r3) {
    asm volatile("ldmatrix.sync.aligned.m8n8.x4.trans.shared.b16 {%0,%1,%2,%3}, [%4];"
                 : "=r"(r0), "=r"(r1), "=r"(r2), "=r"(r3) : "r"(a));
}
__device__ __forceinline__ void mma16816(float* c, u32 a0, u32 a1, u32 a2, u32 a3,
                                         u32 b0, u32 b1) {
    asm volatile("mma.sync.aligned.m16n8k16.row.col.f32.bf16.bf16.f32 "
                 "{%0,%1,%2,%3}, {%4,%5,%6,%7}, {%8,%9}, {%0,%1,%2,%3};"
                 : "+f"(c[0]), "+f"(c[1]), "+f"(c[2]), "+f"(c[3])
                 : "r"(a0), "r"(a1), "r"(a2), "r"(a3), "r"(b0), "r"(b1));
}
__device__ __forceinline__ u16 bfb(__nv_bfloat16 h) { return __bfloat16_as_ushort(h); }
__device__ __forceinline__ u32 pk(__nv_bfloat16 a, __nv_bfloat16 b) {
    return (u32)bfb(a) | ((u32)bfb(b) << 16);
}

extern __shared__ char smem[];

__global__ __launch_bounds__(NTHREADS, 2)
void fv_main_kernel(const float* __restrict__ x,
                    const float* __restrict__ pi,
                    const float* __restrict__ mu,
                    const float* __restrict__ var) {
    const int tid  = threadIdx.x;
    const int bid  = blockIdx.x;
    const int wid  = tid >> 5;
    const int lane = tid & 31;
    const u32 SB = smem_u32(smem);
    float* Lf    = (float*)(smem + SM_STAGE);   // logits view (stride 68 f32)
    float* c_sh  = (float*)(smem + SM_C);
    float* qs_sh = (float*)(smem + SM_QS);

    const int s_lo = (bid * NCHUNK_TOTAL) / GRID;
    const int s_hi = ((bid + 1) * NCHUNK_TOTAL) / GRID;

    // ---- prologue: stage first chunk via cp.async ----
    {
        const float* src = x + (size_t)s_lo * (TT * 64);
        #pragma unroll
        for (int ii = 0; ii < 4; ii++) {
            int j = tid + 256 * ii;                 // 0..1023 float4 slots
            cpasync16(SB + SM_STAGE + (j >> 4) * 272 + (j & 15) * 16, src + j * 4);
        }
        cpcommit();
    }

    // ---- prep: W hi/lo tiles (row k: [Ws(0-63)|Wx(64-127)]) + c const ----
    for (int i = tid; i < 4096; i += NTHREADS) {
        int k = i >> 6, d = i & 63;
        float v = var[i], m = mu[i];
        float iv = __frcp_rn(v);
        float ws = -0.5f * iv * LOG2E, wx = m * iv * LOG2E;
        __nv_bfloat16 wsh = __float2bfloat16(ws);
        __nv_bfloat16 wxh = __float2bfloat16(wx);
        __nv_bfloat16 wsl = __float2bfloat16(ws - __bfloat162float(wsh));
        __nv_bfloat16 wxl = __float2bfloat16(wx - __bfloat162float(wxh));
        *(u16*)(smem + SM_WH + k * 272 + d * 2)       = bfb(wsh);
        *(u16*)(smem + SM_WH + k * 272 + 128 + d * 2) = bfb(wxh);
        *(u16*)(smem + SM_WL + k * 272 + d * 2)       = bfb(wsl);
        *(u16*)(smem + SM_WL + k * 272 + 128 + d * 2) = bfb(wxl);
    }
    {
        int k = tid >> 2, seg = tid & 3;
        float part = 0.f;
        #pragma unroll 4
        for (int d = seg * 16; d < seg * 16 + 16; d++) {
            float v = var[k * 64 + d], m = mu[k * 64 + d];
            part += __logf(v) + m * m * __frcp_rn(v);
        }
        part += __shfl_xor_sync(0xffffffffu, part, 1);
        part += __shfl_xor_sync(0xffffffffu, part, 2);
        if (seg == 0)
            c_sh[k] = (-0.5f * (64.0f * LN2PI + part) + __logf(pi[k])) * LOG2E;
    }
    __syncthreads();

    // warp tiling
    const int mw = wid & 3;        // m-tile (GEMM1: tokens 16mw.. / GEMM2: k rows 16mw..)
    const int qn = wid >> 2;       // n-half
    const int tA = 16 * mw;

    // precomputed ldmatrix bases
    const u32 g1aH = SB + SM_FH + (tA + (lane & 15)) * 272 + (lane >> 4) * 16;
    const u32 g1aL = SB + SM_FL + (tA + (lane & 15)) * 272 + (lane >> 4) * 16;
    u32 g1b[4];
    #pragma unroll
    for (int nt = 0; nt < 4; nt++)
        g1b[nt] = SB + (lane < 16 ? SM_WH : SM_WL)
                + (qn * 32 + nt * 8 + (lane & 7)) * 272 + ((lane >> 3) & 1) * 16;
    const u32 g2aH = SB + SM_QH + ((lane & 7) + ((lane >> 4) << 3)) * 144
                   + mw * 32 + ((lane >> 3) & 1) * 16;
    const u32 g2aL = g2aH + (SM_QL - SM_QH);
    u32 g2b[8];
    #pragma unroll
    for (int nt = 0; nt < 8; nt++)
        g2b[nt] = SB + (lane < 16 ? SM_FH : SM_FL)
                + (lane & 15) * 272 + (64 * qn + nt * 8) * 2;

    const float cl0 = c_sh[lane];
    const float cl1 = c_sh[lane + 32];

    // persistent GEMM2 accumulators + Q_sum
    float c2[8][4];
    #pragma unroll
    for (int i = 0; i < 8; i++)
        #pragma unroll
        for (int j = 0; j < 4; j++) c2[i][j] = 0.f;
    float qs0 = 0.f, qs1 = 0.f;

    int slot = 0;
    int cur_b = s_lo >> 8;

    for (int c = s_lo; c < s_hi; c++) {
        cpwait0();
        __syncthreads();          // stage ready; f/Q free

        // ---- conversion: stage (f32 x) -> f_hi/f_lo bf16 [x^2 | x] ----
        {
            int t = tid >> 2, cg = tid & 3;
            #pragma unroll
            for (int ii = 0; ii < 4; ii++) {
                int c0 = cg * 16 + ii * 4;
                float4 v = *(const float4*)(smem + SM_STAGE + t * 272 + c0 * 4);
                float xs[4] = {v.x, v.y, v.z, v.w};
                u32 ph[2], pl[2], sh2[2], sl2[2];
                #pragma unroll
                for (int j = 0; j < 2; j++) {
                    float a0 = xs[2 * j], a1 = xs[2 * j + 1];
                    __nv_bfloat16 h0 = __float2bfloat16(a0), h1 = __float2bfloat16(a1);
                    ph[j] = pk(h0, h1);
                    pl[j] = pk(__float2bfloat16(a0 - __bfloat162float(h0)),
                               __float2bfloat16(a1 - __bfloat162float(h1)));
                    float s0 = a0 * a0, s1 = a1 * a1;
                    __nv_bfloat16 g0 = __float2bfloat16(s0), g1 = __float2bfloat16(s1);
                    sh2[j] = pk(g0, g1);
                    sl2[j] = pk(__float2bfloat16(s0 - __bfloat162float(g0)),
                                __float2bfloat16(s1 - __bfloat162float(g1)));
                }
                *(uint2*)(smem + SM_FH + t * 272 + 2 * c0)       = make_uint2(sh2[0], sh2[1]);
                *(uint2*)(smem + SM_FL + t * 272 + 2 * c0)       = make_uint2(sl2[0], sl2[1]);
                *(uint2*)(smem + SM_FH + t * 272 + 128 + 2 * c0) = make_uint2(ph[0], ph[1]);
                *(uint2*)(smem + SM_FL + t * 272 + 128 + 2 * c0) = make_uint2(pl[0], pl[1]);
            }
        }
        __syncthreads();

        // ---- GEMM1: logits = f @ W^T  (3 hi/lo products) ----
        {
            float c1[4][4];
            #pragma unroll
            for (int i = 0; i < 4; i++)
                #pragma unroll
                for (int j = 0; j < 4; j++) c1[i][j] = 0.f;

            #pragma unroll
            for (int ks = 0; ks < 8; ks++) {
                u32 ah0, ah1, ah2, ah3, al0, al1, al2, al3;
                ldsm4(g1aH + 32 * ks, ah0, ah1, ah2, ah3);
                ldsm4(g1aL + 32 * ks, al0, al1, al2, al3);
                #pragma unroll
                for (int nt = 0; nt < 4; nt++) {
                    u32 bh0, bh1, bl0, bl1;
                    ldsm4(g1b[nt] + 32 * ks, bh0, bh1, bl0, bl1);
                    mma16816(c1[nt], ah0, ah1, ah2, ah3, bh0, bh1);
                    mma16816(c1[nt], ah0, ah1, ah2, ah3, bl0, bl1);
                    mma16816(c1[nt], al0, al1, al2, al3, bh0, bh1);
                }
            }
            // store logits to L (stage reuse), stride 68 f32
            int r0w = tA + (lane >> 2);
            #pragma unroll
            for (int nt = 0; nt < 4; nt++) {
                int C = qn * 32 + nt * 8 + 2 * (lane & 3);
                *(float2*)(Lf + r0w * 68 + C)       = make_float2(c1[nt][0], c1[nt][1]);
                *(float2*)(Lf + (r0w + 8) * 68 + C) = make_float2(c1[nt][2], c1[nt][3]);
            }
        }
        __syncthreads();

        // ---- softmax (warp per 8 tokens); write Q hi/lo; Q_sum in fp32 ----
        {
            #pragma unroll
            for (int t8 = 0; t8 < 8; t8++) {
                int t = wid * 8 + t8;
                float l0 = Lf[t * 68 + lane] + cl0;
                float l1 = Lf[t * 68 + lane + 32] + cl1;
                float m = fmaxf(l0, l1);
                #pragma unroll
                for (int o = 16; o > 0; o >>= 1)
                    m = fmaxf(m, __shfl_xor_sync(0xffffffffu, m, o));
                float e0 = ex2f(l0 - m);
                float e1 = ex2f(l1 - m);
                float ssum = e0 + e1;
                #pragma unroll
                for (int o = 16; o > 0; o >>= 1)
                    ssum += __shfl_xor_sync(0xffffffffu, ssum, o);
                float inv = __frcp_rn(ssum);
                float q0 = e0 * inv, q1 = e1 * inv;
                __nv_bfloat16 h0 = __float2bfloat16(q0), h1 = __float2bfloat16(q1);
                *(u16*)(smem + SM_QH + t * 144 + lane * 2)      = bfb(h0);
                *(u16*)(smem + SM_QH + t * 144 + 64 + lane * 2) = bfb(h1);
                *(u16*)(smem + SM_QL + t * 144 + lane * 2)      =
                    bfb(__float2bfloat16(q0 - __bfloat162float(h0)));
                *(u16*)(smem + SM_QL + t * 144 + 64 + lane * 2) =
                    bfb(__float2bfloat16(q1 - __bfloat162float(h1)));
                qs0 += q0; qs1 += q1;
            }
        }
        __syncthreads();

        // ---- prefetch next chunk (stage free now; lands during GEMM2) ----
        if (c + 1 < s_hi) {
            const float* src = x + (size_t)(c + 1) * (TT * 64);
            #pragma unroll
            for (int ii = 0; ii < 4; ii++) {
                int j = tid + 256 * ii;
                cpasync16(SB + SM_STAGE + (j >> 4) * 272 + (j & 15) * 16, src + j * 4);
            }
            cpcommit();
        }

        // ---- GEMM2: [Qx2|Qx] += Q^T @ [x^2|x]  (3 hi/lo products) ----
        {
            #pragma unroll
            for (int ks = 0; ks < 4; ks++) {
                u32 qh0, qh1, qh2, qh3, ql0, ql1, ql2, ql3;
                ldsm4t(g2aH + 2304 * ks, qh0, qh1, qh2, qh3);
                ldsm4t(g2aL + 2304 * ks, ql0, ql1, ql2, ql3);
                #pragma unroll
                for (int nt = 0; nt < 8; nt++) {
                    u32 bh0, bh1, bl0, bl1;
                    ldsm4t(g2b[nt] + 4352 * ks, bh0, bh1, bl0, bl1);
                    mma16816(c2[nt], qh0, qh1, qh2, qh3, bh0, bh1);
                    mma16816(c2[nt], qh0, qh1, qh2, qh3, bl0, bl1);
                    mma16816(c2[nt], ql0, ql1, ql2, ql3, bh0, bh1);
                }
            }
        }

        // ---- segment flush ----
        int nb = (c + 1) >> 8;
        if (c + 1 == s_hi || nb != cur_b) {
            qs_sh[wid * 66 + lane]      = qs0;
            qs_sh[wid * 66 + lane + 32] = qs1;
            __syncthreads();
            float* outp = g_scratch + (size_t)(bid * 2 + slot) * PSIZE;
            if (tid == 0) g_tag[bid * 2 + slot] = cur_b;
            if (tid < 64) {
                float s = 0.f;
                #pragma unroll
                for (int w = 0; w < 8; w++) s += qs_sh[w * 66 + tid];
                outp[tid] = s;
            }
            int kr = mw * 16 + (lane >> 2);
            #pragma unroll
            for (int nt = 0; nt < 8; nt++) {
                int C = 64 * qn + nt * 8 + 2 * (lane & 3);
                float* dst = (C < 64) ? (outp + 64 + 4096 + kr * 64 + C)
                                      : (outp + 64 + kr * 64 + (C - 64));
                *(float2*)dst            = make_float2(c2[nt][0], c2[nt][1]);
                *(float2*)(dst + 8 * 64) = make_float2(c2[nt][2], c2[nt][3]);
                c2[nt][0] = 0.f; c2[nt][1] = 0.f; c2[nt][2] = 0.f; c2[nt][3] = 0.f;
            }
            qs0 = 0.f; qs1 = 0.f;
            slot++;
            cur_b = nb;
            __syncthreads();
        }
    }
    if (tid == 0) {
        for (int sl = slot; sl < 2; sl++) g_tag[bid * 2 + sl] = -1;
    }
}

// ---------------- reduce + finalize ------------------------------
__global__ void fv_reduce_kernel(const float* __restrict__ pi,
                                 const float* __restrict__ mu,
                                 const float* __restrict__ var,
                                 float* __restrict__ out) {
    int idx = blockIdx.x * blockDim.x + threadIdx.x;
    if (idx >= BB * 64 * 64) return;
    int b = idx >> 12, kd = idx & 4095, k = kd >> 6, d = kd & 63;
    int i_lo = (GRID * b) / BB - 1;       if (i_lo < 0) i_lo = 0;
    int i_hi = (GRID * (b + 1)) / BB + 1; if (i_hi > GRID - 1) i_hi = GRID - 1;
    float qs = 0.f, qx = 0.f, qx2 = 0.f;
    for (int i = i_lo; i <= i_hi; i++) {
        #pragma unroll
        for (int sl = 0; sl < 2; sl++) {
            int sid = 2 * i + sl;
            if (g_tag[sid] == b) {
                const float* p = g_scratch + (size_t)sid * PSIZE;
                qs += p[k]; qx += p[64 + kd]; qx2 += p[64 + 4096 + kd];
            }
        }
    }
    const float invN = 1.0f / (float)NTOK;
    qs *= invN; qx *= invN; qx2 *= invN;
    float m = mu[kd], v = var[kd];
    float* ob = out + (size_t)b * 8256;
    ob[64 + kd]        = qx - qs * m;
    ob[64 + 4096 + kd] = -qx2 - qs * m * m + qs * v + 2.0f * qx * m;
    if (d == 0) ob[k] = qs - pi[k];
}

extern "C" void kernel_launch(void* const* d_in, const int* in_sizes, int n_in,
                              void* d_out, int out_size) {
    const float* x   = (const float*)d_in[0];
    const float* pi  = (const float*)d_in[1];
    const float* mu  = (const float*)d_in[2];
    const float* var = (const float*)d_in[3];
    float* out = (float*)d_out;
    cudaFuncSetAttribute(fv_main_kernel,
                         cudaFuncAttributeMaxDynamicSharedMemorySize, SMEM_BYTES);
    fv_main_kernel<<<GRID, NTHREADS, SMEM_BYTES>>>(x, pi, mu, var);
    fv_reduce_kernel<<<(BB * 64 * 64 + 255) / 256, 256>>>(pi, mu, var, out);
}